// round 14
// baseline (speedup 1.0000x reference)
#include <cuda_runtime.h>

// ---------------------------------------------------------------------------
// CumulantSOAP, fused single kernel, distributed finish:
//   phase 1 (592 blocks, 4/SM all-resident): streaming raw moments ->
//            g_partial[m][b][col]; arrive on per-slice counter (8 slices x 74).
//   phase 2 (blocks 0..255 = 32 colgrps x 8 slices): spin on OWN slice
//            counter, fold 74 partials -> g_partial2[m][slice][col].
//   phase 3 (per-colgrp last reducer, x32 in parallel): fold 8 slices for its
//            32 columns, fp32 cumulants, (c - mu) @ W slice -> g_outp[cg][8].
//   phase 4 (last colgrp finisher): sum 32 partial outputs -> out, reset.
// __launch_bounds__(256,5) caps regs at ~51 so the phase-1 streaming loop
// compiles identically to the fast standalone version; phase-2/3 spills are
// confined to <=256 short-lived blocks.
// Deterministic: fixed membership + fixed summation order at every level.
// Deadlock-free: all blocks co-resident; the single spin targets counters
// every phase-1 block increments unconditionally; rest is continuation.
// ---------------------------------------------------------------------------

#define NM    5
#define GTOT  592        // 148 SMs x 4 blocks, all resident
#define PMAX  1024
#define NSLC  8
#define CHUNK 74         // 592 / 8 exactly

__device__ float g_partial [NM * GTOT * PMAX];   // [m][b][col]
__device__ float g_partial2[NM * NSLC * PMAX];   // [m][slice][col]
__device__ float g_outp[32 * 8];                 // per-colgrp partial outputs
__device__ float g_cum[NM * PMAX];               // generic-fallback only
__device__ unsigned g_cslice[NSLC];              // per-slice phase-1 arrivals
__device__ unsigned g_cgrp[32];                  // per-colgrp reducer tickets
__device__ unsigned g_cnt3 = 0;                  // colgrp-finisher tickets

// ---- packed f32x2 helpers (Blackwell FFMA2 path, PTX-only) ----------------
static __device__ __forceinline__ unsigned long long f2_mul(unsigned long long a,
                                                            unsigned long long b) {
    unsigned long long d;
    asm("mul.rn.f32x2 %0, %1, %2;" : "=l"(d) : "l"(a), "l"(b));
    return d;
}
static __device__ __forceinline__ unsigned long long f2_add(unsigned long long a,
                                                            unsigned long long b) {
    unsigned long long d;
    asm("add.rn.f32x2 %0, %1, %2;" : "=l"(d) : "l"(a), "l"(b));
    return d;
}
static __device__ __forceinline__ unsigned long long f2_fma(unsigned long long a,
                                                            unsigned long long b,
                                                            unsigned long long c) {
    unsigned long long d;
    asm("fma.rn.f32x2 %0, %1, %2, %3;" : "=l"(d) : "l"(a), "l"(b), "l"(c));
    return d;
}
static __device__ __forceinline__ float2 f2_unpack(unsigned long long v) {
    float2 f;
    asm("mov.b64 {%0, %1}, %2;" : "=f"(f.x), "=f"(f.y) : "l"(v));
    return f;
}

#define ACC(u, s1, s2, s3, s4, s5)                         \
    do {                                                   \
        unsigned long long _x2 = f2_mul((u), (u));         \
        unsigned long long _x3 = f2_mul(_x2, (u));         \
        (s1) = f2_add((s1), (u));                          \
        (s2) = f2_fma((u), (u), (s2));                     \
        (s3) = f2_fma(_x2, (u), (s3));                     \
        (s4) = f2_fma(_x2, _x2, (s4));                     \
        (s5) = f2_fma(_x3, _x2, (s5));                     \
    } while (0)

// ---------------------------------------------------------------------------
__global__ __launch_bounds__(256, 5)
void k_fused(const float* __restrict__ X, const float* __restrict__ mu,
             const float* __restrict__ W, float* __restrict__ out, int N) {
    const int b = blockIdx.x;
    const int tid = threadIdx.x;
    const int P = PMAX;
    const int G = GTOT;

    // ================= phase 1: streaming raw moments =================
    {
        const int col4 = tid * 4;
        unsigned long long s1a = 0ULL, s2a = 0ULL, s3a = 0ULL, s4a = 0ULL, s5a = 0ULL;
        unsigned long long s1b = 0ULL, s2b = 0ULL, s3b = 0ULL, s4b = 0ULL, s5b = 0ULL;

        const char* base = (const char*)(X + col4);
        const size_t rowBytes = (size_t)P * sizeof(float);

        int r = b;
        const int G4 = 4 * G;
        for (; r + 3 * G < N; r += G4) {
            ulonglong2 v0 = *(const ulonglong2*)(base + (size_t)r * rowBytes);
            ulonglong2 v1 = *(const ulonglong2*)(base + (size_t)(r + G) * rowBytes);
            ulonglong2 v2 = *(const ulonglong2*)(base + (size_t)(r + 2 * G) * rowBytes);
            ulonglong2 v3 = *(const ulonglong2*)(base + (size_t)(r + 3 * G) * rowBytes);
            ACC(v0.x, s1a, s2a, s3a, s4a, s5a);
            ACC(v0.y, s1b, s2b, s3b, s4b, s5b);
            ACC(v1.x, s1a, s2a, s3a, s4a, s5a);
            ACC(v1.y, s1b, s2b, s3b, s4b, s5b);
            ACC(v2.x, s1a, s2a, s3a, s4a, s5a);
            ACC(v2.y, s1b, s2b, s3b, s4b, s5b);
            ACC(v3.x, s1a, s2a, s3a, s4a, s5a);
            ACC(v3.y, s1b, s2b, s3b, s4b, s5b);
        }
        for (; r < N; r += G) {
            ulonglong2 v = *(const ulonglong2*)(base + (size_t)r * rowBytes);
            ACC(v.x, s1a, s2a, s3a, s4a, s5a);
            ACC(v.y, s1b, s2b, s3b, s4b, s5b);
        }

        const size_t GP = (size_t)G * P;
        float* o = g_partial + (size_t)b * P + col4;
        float2 a, bb;
        a = f2_unpack(s1a); bb = f2_unpack(s1b);
        *(float4*)(o + 0 * GP) = make_float4(a.x, a.y, bb.x, bb.y);
        a = f2_unpack(s2a); bb = f2_unpack(s2b);
        *(float4*)(o + 1 * GP) = make_float4(a.x, a.y, bb.x, bb.y);
        a = f2_unpack(s3a); bb = f2_unpack(s3b);
        *(float4*)(o + 2 * GP) = make_float4(a.x, a.y, bb.x, bb.y);
        a = f2_unpack(s4a); bb = f2_unpack(s4b);
        *(float4*)(o + 3 * GP) = make_float4(a.x, a.y, bb.x, bb.y);
        a = f2_unpack(s5a); bb = f2_unpack(s5b);
        *(float4*)(o + 4 * GP) = make_float4(a.x, a.y, bb.x, bb.y);
    }

    // ================= arrival (per-slice) =================
    __threadfence();
    __syncthreads();
    if (tid == 0) atomicAdd(&g_cslice[b / CHUNK], 1u);

    if (b >= 32 * NSLC) return;            // 256 reducer blocks continue

    const int gs = b >> 5;                 // slice 0..7
    const int colgrp = b & 31;             // 0..31
    const int cl = tid & 31;
    const int p  = tid >> 5;               // 0..7
    const int col = colgrp * 32 + cl;

    // ================= phase 2: wait for OWN slice, reduce 74 partials =====
    if (tid == 0) {
        while (*(volatile unsigned*)&g_cslice[gs] < (unsigned)CHUNK) __nanosleep(64);
    }
    __syncthreads();
    __threadfence();                        // order partial reads after spin

    {
        const int b0 = gs * CHUNK;
        const int b1 = b0 + CHUNK;
        const size_t GP = (size_t)G * P;

        float acc[NM] = {0.f, 0.f, 0.f, 0.f, 0.f};
#pragma unroll 2
        for (int bb = b0 + p; bb < b1; bb += 8) {
            const size_t off = (size_t)bb * P + col;
#pragma unroll
            for (int m = 0; m < NM; m++)
                acc[m] += g_partial[(size_t)m * GP + off];
        }

        __shared__ float smem[NM][8][32];
#pragma unroll
        for (int m = 0; m < NM; m++) smem[m][p][cl] = acc[m];
        __syncthreads();

        if (p == 0) {
#pragma unroll
            for (int m = 0; m < NM; m++) {
                float v = 0.f;
#pragma unroll
                for (int j = 0; j < 8; j++) v += smem[m][j][cl];
                g_partial2[(size_t)m * (NSLC * PMAX) + (size_t)gs * PMAX + col] = v;
            }
        }
    }

    __threadfence();
    __syncthreads();

    __shared__ unsigned s_tkt;
    if (tid == 0) s_tkt = atomicAdd(&g_cgrp[colgrp], 1u);
    __syncthreads();
    if (s_tkt != NSLC - 1) return;          // per-colgrp LAST reducer continues

    // ================= phase 3: colgrp finish (32 cols, x32 parallel) ======
    __threadfence();                        // acquire all 8 slices of colgrp

    // W slice load: thread (cl, p) needs W[col*40 + q*8 + p], q=0..4
    float wv[NM];
#pragma unroll
    for (int q = 0; q < NM; q++)
        wv[q] = __ldg(&W[(size_t)col * 40 + q * 8 + p]);

    // thread (cl, p) loads slice p for its column
    __shared__ float sm2[NM][8][32];
#pragma unroll
    for (int m = 0; m < NM; m++)
        sm2[m][p][cl] = g_partial2[(size_t)m * (NSLC * PMAX) + (size_t)p * PMAX + col];
    __syncthreads();

    __shared__ float scm[NM][32];
    if (p == 0) {
        const float* mup = mu + (size_t)col * NM;    // unaligned: scalars
        float muv[NM];
#pragma unroll
        for (int q = 0; q < NM; q++) muv[q] = __ldg(&mup[q]);

        float t[NM];
#pragma unroll
        for (int m = 0; m < NM; m++) {
            float v = 0.f;
#pragma unroll
            for (int j = 0; j < 8; j++) v += sm2[m][j][cl];
            t[m] = v;
        }
        const float invN = 1.0f / (float)N;
        const float m1 = t[0] * invN;
        const float r2 = t[1] * invN;
        const float r3 = t[2] * invN;
        const float r4 = t[3] * invN;
        const float r5 = t[4] * invN;
        const float m2 = m1 * m1;
        const float m3 = m2 * m1;

        const float mu2 = r2 - m2;
        const float mu3 = r3 - 3.0f * m1 * r2 + 2.0f * m3;
        const float mu5 = r5 - 5.0f * m1 * r4 + 10.0f * m2 * r3 - 10.0f * m3 * r2
                          + 4.0f * m3 * m2;

        scm[0][cl] = m1                        - muv[0];
        scm[1][cl] = 0.f                       - muv[1];   // mean(centered) == 0
        scm[2][cl] = mu2                       - muv[2];
        scm[3][cl] = (mu3 - 3.0f * mu2 * mu2)  - muv[3];
        scm[4][cl] = (mu5 - 10.0f * mu2 * mu3) - muv[4];
    }
    __syncthreads();

    // projection slice: warp p computes output k=p over these 32 cols
    float a = 0.f;
#pragma unroll
    for (int q = 0; q < NM; q++)
        a += scm[q][cl] * wv[q];
#pragma unroll
    for (int o = 16; o > 0; o >>= 1)
        a += __shfl_down_sync(0xffffffffu, a, o);
    if (cl == 0) g_outp[colgrp * 8 + p] = a;

    __threadfence();
    __syncthreads();
    if (tid == 0) s_tkt = atomicAdd(&g_cnt3, 1u);
    __syncthreads();
    if (s_tkt != 31) return;                // LAST colgrp finisher remains

    // ================= phase 4: final sum + counter reset ==================
    __threadfence();
    if (tid < 8) {
        float v = 0.f;
#pragma unroll
        for (int i = 0; i < 32; i++) v += g_outp[i * 8 + tid];
        out[tid] = v;
    }
    if (tid < NSLC) g_cslice[tid] = 0;
    if (tid < 32)   g_cgrp[tid] = 0;
    if (tid == 0)   g_cnt3 = 0;
    __threadfence();
}

// ---------------------------------------------------------------------------
// Generic fallback path (K != 8 or P != 1024): 3 separate kernels, fp32.
// ---------------------------------------------------------------------------
__global__ __launch_bounds__(256, 4)
void k_moments(const float* __restrict__ X, int N, int P, int G) {
    const int b = blockIdx.x;
    const int tid = threadIdx.x;
    const int col4 = tid * 4;

    unsigned long long s1a = 0ULL, s2a = 0ULL, s3a = 0ULL, s4a = 0ULL, s5a = 0ULL;
    unsigned long long s1b = 0ULL, s2b = 0ULL, s3b = 0ULL, s4b = 0ULL, s5b = 0ULL;

    const char* base = (const char*)(X + col4);
    const size_t rowBytes = (size_t)P * sizeof(float);

    for (int r = b; r < N; r += G) {
        ulonglong2 v = *(const ulonglong2*)(base + (size_t)r * rowBytes);
        ACC(v.x, s1a, s2a, s3a, s4a, s5a);
        ACC(v.y, s1b, s2b, s3b, s4b, s5b);
    }

    const size_t GP = (size_t)G * P;
    float* o = g_partial + (size_t)b * P + col4;
    float2 a, bb;
    a = f2_unpack(s1a); bb = f2_unpack(s1b);
    *(float4*)(o + 0 * GP) = make_float4(a.x, a.y, bb.x, bb.y);
    a = f2_unpack(s2a); bb = f2_unpack(s2b);
    *(float4*)(o + 1 * GP) = make_float4(a.x, a.y, bb.x, bb.y);
    a = f2_unpack(s3a); bb = f2_unpack(s3b);
    *(float4*)(o + 2 * GP) = make_float4(a.x, a.y, bb.x, bb.y);
    a = f2_unpack(s4a); bb = f2_unpack(s4b);
    *(float4*)(o + 3 * GP) = make_float4(a.x, a.y, bb.x, bb.y);
    a = f2_unpack(s5a); bb = f2_unpack(s5b);
    *(float4*)(o + 4 * GP) = make_float4(a.x, a.y, bb.x, bb.y);
}

__global__ __launch_bounds__(128)
void k_reduceB_gen(const float* __restrict__ mu, int N, int P, int G) {
    const int col = blockIdx.x * 128 + threadIdx.x;
    if (col >= P) return;
    const size_t GP = (size_t)G * P;

    float t[NM] = {0.f, 0.f, 0.f, 0.f, 0.f};
    for (int bb = 0; bb < G; bb++) {
#pragma unroll
        for (int m = 0; m < NM; m++)
            t[m] += g_partial[(size_t)m * GP + (size_t)bb * P + col];
    }

    const float invN = 1.0f / (float)N;
    const float m1 = t[0] * invN;
    const float r2 = t[1] * invN;
    const float r3 = t[2] * invN;
    const float r4 = t[3] * invN;
    const float r5 = t[4] * invN;
    const float m2 = m1 * m1;
    const float m3 = m2 * m1;

    const float mu2 = r2 - m2;
    const float mu3 = r3 - 3.0f * m1 * r2 + 2.0f * m3;
    const float mu5 = r5 - 5.0f * m1 * r4 + 10.0f * m2 * r3 - 10.0f * m3 * r2
                      + 4.0f * m3 * m2;

    const int j = col * NM;
    g_cum[j + 0] = m1 - mu[j + 0];
    g_cum[j + 1] = 0.f - mu[j + 1];
    g_cum[j + 2] = mu2 - mu[j + 2];
    g_cum[j + 3] = (mu3 - 3.0f * mu2 * mu2) - mu[j + 3];
    g_cum[j + 4] = (mu5 - 10.0f * mu2 * mu3) - mu[j + 4];
}

__global__ void k_project_gen(const float* __restrict__ W, float* __restrict__ out,
                              int P5, int K) {
    const int w = blockIdx.x;
    const int lane = threadIdx.x;
    float acc = 0.f;
    for (int i = lane; i < P5; i += 32)
        acc += g_cum[i] * W[(size_t)i * K + w];
#pragma unroll
    for (int o = 16; o > 0; o >>= 1)
        acc += __shfl_down_sync(0xffffffffu, acc, o);
    if (lane == 0) out[w] = acc;
}

// ---------------------------------------------------------------------------
extern "C" void kernel_launch(void* const* d_in, const int* in_sizes, int n_in,
                              void* d_out, int out_size) {
    const float* X  = (const float*)d_in[0];
    const float* mu = (const float*)d_in[1];
    const float* W  = (const float*)d_in[2];
    float* out = (float*)d_out;

    const int P5 = in_sizes[1];          // P * 5
    const int P  = P5 / NM;              // 1024
    const int N  = in_sizes[0] / P;      // 100000
    const int K  = in_sizes[2] / P5;     // 8

    if (K == 8 && P == 1024) {
        k_fused<<<GTOT, 256>>>(X, mu, W, out, N);
    } else {
        const int Gg = GTOT;
        k_moments<<<Gg, P / 4>>>(X, N, P, Gg);
        k_reduceB_gen<<<(P + 127) / 128, 128>>>(mu, N, P, Gg);
        k_project_gen<<<K, 32>>>(W, out, P5, K);
    }
}

// round 15
// speedup vs baseline: 1.0526x; 1.0526x over previous
#include <cuda_runtime.h>

// ---------------------------------------------------------------------------
// CumulantSOAP, fused single kernel, colstripe layout, ZERO spins:
//   phase 1 (592 blocks = 8 colstripes x 74 rowchunks): each block streams
//     rows of its chunk for its 128 columns (8 warps x different rows, same
//     cols), folds 8 warps in smem, writes 5x128 floats -> g_partial
//     (total 1.5 MB, L2-resident).
//   finish (per-colstripe LAST arriver, x8 in parallel, pure continuation):
//     folds 74 chunk-partials for its 128 cols (L2-hot, 8-way + smem),
//     fp32 cumulants, (c - mu) @ W slice -> g_outp[cs][8].
//   final (last of the 8): sums partial outputs -> out, resets counters.
// Deterministic: fixed membership + fixed summation order at every level.
// Deadlock-free: pure ticket-continuation, no spin loops at all.
// ---------------------------------------------------------------------------

#define NM    5
#define NCS   8          // colstripes of 128 columns
#define NRC   74         // rowchunks
#define GTOT  (NCS * NRC)   // 592
#define PMAX  1024

__device__ float g_partial[NM * NRC * PMAX];     // [m][rc][col]  (1.5 MB)
__device__ float g_outp[NCS * 8];                // per-colstripe partial outputs
__device__ float g_cum[NM * PMAX];               // generic-fallback only
__device__ unsigned g_ccs[NCS];                  // per-colstripe arrivals
__device__ unsigned g_cnt3 = 0;                  // finisher tickets
// fallback scratch (separate, larger)
__device__ float g_partialF[NM * GTOT * PMAX];

// ---- packed f32x2 helpers (Blackwell FFMA2 path, PTX-only) ----------------
static __device__ __forceinline__ unsigned long long f2_mul(unsigned long long a,
                                                            unsigned long long b) {
    unsigned long long d;
    asm("mul.rn.f32x2 %0, %1, %2;" : "=l"(d) : "l"(a), "l"(b));
    return d;
}
static __device__ __forceinline__ unsigned long long f2_add(unsigned long long a,
                                                            unsigned long long b) {
    unsigned long long d;
    asm("add.rn.f32x2 %0, %1, %2;" : "=l"(d) : "l"(a), "l"(b));
    return d;
}
static __device__ __forceinline__ unsigned long long f2_fma(unsigned long long a,
                                                            unsigned long long b,
                                                            unsigned long long c) {
    unsigned long long d;
    asm("fma.rn.f32x2 %0, %1, %2, %3;" : "=l"(d) : "l"(a), "l"(b), "l"(c));
    return d;
}
static __device__ __forceinline__ float2 f2_unpack(unsigned long long v) {
    float2 f;
    asm("mov.b64 {%0, %1}, %2;" : "=f"(f.x), "=f"(f.y) : "l"(v));
    return f;
}

#define ACC(u, s1, s2, s3, s4, s5)                         \
    do {                                                   \
        unsigned long long _x2 = f2_mul((u), (u));         \
        unsigned long long _x3 = f2_mul(_x2, (u));         \
        (s1) = f2_add((s1), (u));                          \
        (s2) = f2_fma((u), (u), (s2));                     \
        (s3) = f2_fma(_x2, (u), (s3));                     \
        (s4) = f2_fma(_x2, _x2, (s4));                     \
        (s5) = f2_fma(_x3, _x2, (s5));                     \
    } while (0)

// ---------------------------------------------------------------------------
__global__ __launch_bounds__(256, 4)
void k_fused(const float* __restrict__ X, const float* __restrict__ mu,
             const float* __restrict__ W, float* __restrict__ out, int N) {
    const int b   = blockIdx.x;
    const int tid = threadIdx.x;
    const int cs  = b & (NCS - 1);        // colstripe 0..7
    const int rc  = b >> 3;               // rowchunk 0..73
    const int w   = tid >> 5;             // warp 0..7
    const int l   = tid & 31;             // lane

    __shared__ float s_buf[8 * NM * 128]; // 20 KB, reused across phases
    __shared__ float s_cm[NM * 128];      // cumulants - mu
    __shared__ unsigned s_tkt;

    const int chunk = (N + NRC - 1) / NRC;

    // ================= phase 1: streaming raw moments =================
    {
        const int col4 = cs * 128 + l * 4;
        unsigned long long s1a = 0ULL, s2a = 0ULL, s3a = 0ULL, s4a = 0ULL, s5a = 0ULL;
        unsigned long long s1b = 0ULL, s2b = 0ULL, s3b = 0ULL, s4b = 0ULL, s5b = 0ULL;

        const char* base = (const char*)(X + col4);
        const size_t rowBytes = (size_t)PMAX * sizeof(float);

        const int r1 = min(N, rc * chunk + chunk);
        int r = rc * chunk + w;
        for (; r + 24 < r1; r += 32) {     // 4 rows/thread in flight (step 8)
            ulonglong2 v0 = *(const ulonglong2*)(base + (size_t)r * rowBytes);
            ulonglong2 v1 = *(const ulonglong2*)(base + (size_t)(r + 8) * rowBytes);
            ulonglong2 v2 = *(const ulonglong2*)(base + (size_t)(r + 16) * rowBytes);
            ulonglong2 v3 = *(const ulonglong2*)(base + (size_t)(r + 24) * rowBytes);
            ACC(v0.x, s1a, s2a, s3a, s4a, s5a);
            ACC(v0.y, s1b, s2b, s3b, s4b, s5b);
            ACC(v1.x, s1a, s2a, s3a, s4a, s5a);
            ACC(v1.y, s1b, s2b, s3b, s4b, s5b);
            ACC(v2.x, s1a, s2a, s3a, s4a, s5a);
            ACC(v2.y, s1b, s2b, s3b, s4b, s5b);
            ACC(v3.x, s1a, s2a, s3a, s4a, s5a);
            ACC(v3.y, s1b, s2b, s3b, s4b, s5b);
        }
        for (; r < r1; r += 8) {
            ulonglong2 v = *(const ulonglong2*)(base + (size_t)r * rowBytes);
            ACC(v.x, s1a, s2a, s3a, s4a, s5a);
            ACC(v.y, s1b, s2b, s3b, s4b, s5b);
        }

        // write lane moments to smem: s_buf[w][m][l*4..l*4+3]
        float2 a, bb;
        a = f2_unpack(s1a); bb = f2_unpack(s1b);
        *(float4*)&s_buf[w * (NM * 128) + 0 * 128 + l * 4] = make_float4(a.x, a.y, bb.x, bb.y);
        a = f2_unpack(s2a); bb = f2_unpack(s2b);
        *(float4*)&s_buf[w * (NM * 128) + 1 * 128 + l * 4] = make_float4(a.x, a.y, bb.x, bb.y);
        a = f2_unpack(s3a); bb = f2_unpack(s3b);
        *(float4*)&s_buf[w * (NM * 128) + 2 * 128 + l * 4] = make_float4(a.x, a.y, bb.x, bb.y);
        a = f2_unpack(s4a); bb = f2_unpack(s4b);
        *(float4*)&s_buf[w * (NM * 128) + 3 * 128 + l * 4] = make_float4(a.x, a.y, bb.x, bb.y);
        a = f2_unpack(s5a); bb = f2_unpack(s5b);
        *(float4*)&s_buf[w * (NM * 128) + 4 * 128 + l * 4] = make_float4(a.x, a.y, bb.x, bb.y);
    }
    __syncthreads();

    // fold 8 warps -> write 5 x 128 floats (warp m handles moment m)
    if (w < NM) {
        float4 acc = make_float4(0.f, 0.f, 0.f, 0.f);
#pragma unroll
        for (int j = 0; j < 8; j++) {
            const float4 v = *(const float4*)&s_buf[j * (NM * 128) + w * 128 + l * 4];
            acc.x += v.x; acc.y += v.y; acc.z += v.z; acc.w += v.w;
        }
        *(float4*)&g_partial[w * (NRC * PMAX) + rc * PMAX + cs * 128 + l * 4] = acc;
    }

    // ================= arrival (per-colstripe), pure continuation ==========
    __threadfence();
    __syncthreads();
    if (tid == 0) s_tkt = atomicAdd(&g_ccs[cs], 1u);
    __syncthreads();
    if (s_tkt != NRC - 1) return;          // only the LAST chunk of each stripe

    // ================= finish: fold 74 chunks for this stripe ==============
    __threadfence();                        // acquire all chunk writes

    {
        const int q = tid & 31;             // col-quad 0..31 (4 cols each)
        const int y = tid >> 5;             // way 0..7
        float4 acc[NM];
#pragma unroll
        for (int m = 0; m < NM; m++) acc[m] = make_float4(0.f, 0.f, 0.f, 0.f);

        for (int j = y; j < NRC; j += 8) {
#pragma unroll
            for (int m = 0; m < NM; m++) {
                const float4 v = *(const float4*)
                    &g_partial[m * (NRC * PMAX) + j * PMAX + cs * 128 + q * 4];
                acc[m].x += v.x; acc[m].y += v.y; acc[m].z += v.z; acc[m].w += v.w;
            }
        }
        // s_buf reuse: [m][y][128]
        __syncthreads();                    // re-use s_buf safely
#pragma unroll
        for (int m = 0; m < NM; m++)
            *(float4*)&s_buf[m * (8 * 128) + y * 128 + q * 4] = acc[m];
    }
    __syncthreads();

    // cumulants for 128 columns (threads 0..127)
    if (tid < 128) {
        const int lc = tid;
        const int col = cs * 128 + lc;
        float t[NM];
#pragma unroll
        for (int m = 0; m < NM; m++) {
            float v = 0.f;
#pragma unroll
            for (int j = 0; j < 8; j++) v += s_buf[m * (8 * 128) + j * 128 + lc];
            t[m] = v;
        }
        const float invN = 1.0f / (float)N;
        const float m1 = t[0] * invN;
        const float r2 = t[1] * invN;
        const float r3 = t[2] * invN;
        const float r4 = t[3] * invN;
        const float r5 = t[4] * invN;
        const float m2 = m1 * m1;
        const float m3 = m2 * m1;

        const float mu2 = r2 - m2;
        const float mu3 = r3 - 3.0f * m1 * r2 + 2.0f * m3;
        const float mu5 = r5 - 5.0f * m1 * r4 + 10.0f * m2 * r3 - 10.0f * m3 * r2
                          + 4.0f * m3 * m2;

        const float* mup = mu + (size_t)col * NM;    // unaligned: scalars
        s_cm[0 * 128 + lc] = m1                        - __ldg(&mup[0]);
        s_cm[1 * 128 + lc] = 0.f                       - __ldg(&mup[1]);
        s_cm[2 * 128 + lc] = mu2                       - __ldg(&mup[2]);
        s_cm[3 * 128 + lc] = (mu3 - 3.0f * mu2 * mu2)  - __ldg(&mup[3]);
        s_cm[4 * 128 + lc] = (mu5 - 10.0f * mu2 * mu3) - __ldg(&mup[4]);
    }
    __syncthreads();

    // projection: warp p -> output k=p over this stripe's 128 cols
    {
        const int p = w;                    // 0..7
        float a = 0.f;
#pragma unroll
        for (int g4 = 0; g4 < 4; g4++) {
            const int lc = l + g4 * 32;
            const int col = cs * 128 + lc;
#pragma unroll
            for (int q = 0; q < NM; q++)
                a += s_cm[q * 128 + lc] * __ldg(&W[(size_t)col * 40 + q * 8 + p]);
        }
#pragma unroll
        for (int o = 16; o > 0; o >>= 1)
            a += __shfl_down_sync(0xffffffffu, a, o);
        if (l == 0) g_outp[cs * 8 + p] = a;
    }

    __threadfence();
    __syncthreads();
    if (tid == 0) s_tkt = atomicAdd(&g_cnt3, 1u);
    __syncthreads();
    if (s_tkt != NCS - 1) return;           // only the LAST finisher remains

    // ================= final: sum 8 partial outputs + reset ================
    __threadfence();
    if (tid < 8) {
        float v = 0.f;
#pragma unroll
        for (int i = 0; i < NCS; i++) v += g_outp[i * 8 + tid];
        out[tid] = v;
    }
    if (tid < NCS) g_ccs[tid] = 0;
    if (tid == 0)  g_cnt3 = 0;
    __threadfence();
}

// ---------------------------------------------------------------------------
// Generic fallback path (K != 8 or P != 1024): 3 separate kernels, fp32.
// ---------------------------------------------------------------------------
__global__ __launch_bounds__(256, 4)
void k_moments(const float* __restrict__ X, int N, int P, int G) {
    const int b = blockIdx.x;
    const int tid = threadIdx.x;
    const int col4 = tid * 4;

    unsigned long long s1a = 0ULL, s2a = 0ULL, s3a = 0ULL, s4a = 0ULL, s5a = 0ULL;
    unsigned long long s1b = 0ULL, s2b = 0ULL, s3b = 0ULL, s4b = 0ULL, s5b = 0ULL;

    const char* base = (const char*)(X + col4);
    const size_t rowBytes = (size_t)P * sizeof(float);

    for (int r = b; r < N; r += G) {
        ulonglong2 v = *(const ulonglong2*)(base + (size_t)r * rowBytes);
        ACC(v.x, s1a, s2a, s3a, s4a, s5a);
        ACC(v.y, s1b, s2b, s3b, s4b, s5b);
    }

    const size_t GP = (size_t)G * P;
    float* o = g_partialF + (size_t)b * P + col4;
    float2 a, bb;
    a = f2_unpack(s1a); bb = f2_unpack(s1b);
    *(float4*)(o + 0 * GP) = make_float4(a.x, a.y, bb.x, bb.y);
    a = f2_unpack(s2a); bb = f2_unpack(s2b);
    *(float4*)(o + 1 * GP) = make_float4(a.x, a.y, bb.x, bb.y);
    a = f2_unpack(s3a); bb = f2_unpack(s3b);
    *(float4*)(o + 2 * GP) = make_float4(a.x, a.y, bb.x, bb.y);
    a = f2_unpack(s4a); bb = f2_unpack(s4b);
    *(float4*)(o + 3 * GP) = make_float4(a.x, a.y, bb.x, bb.y);
    a = f2_unpack(s5a); bb = f2_unpack(s5b);
    *(float4*)(o + 4 * GP) = make_float4(a.x, a.y, bb.x, bb.y);
}

__global__ __launch_bounds__(128)
void k_reduceB_gen(const float* __restrict__ mu, int N, int P, int G) {
    const int col = blockIdx.x * 128 + threadIdx.x;
    if (col >= P) return;
    const size_t GP = (size_t)G * P;

    float t[NM] = {0.f, 0.f, 0.f, 0.f, 0.f};
    for (int bb = 0; bb < G; bb++) {
#pragma unroll
        for (int m = 0; m < NM; m++)
            t[m] += g_partialF[(size_t)m * GP + (size_t)bb * P + col];
    }

    const float invN = 1.0f / (float)N;
    const float m1 = t[0] * invN;
    const float r2 = t[1] * invN;
    const float r3 = t[2] * invN;
    const float r4 = t[3] * invN;
    const float r5 = t[4] * invN;
    const float m2 = m1 * m1;
    const float m3 = m2 * m1;

    const float mu2 = r2 - m2;
    const float mu3 = r3 - 3.0f * m1 * r2 + 2.0f * m3;
    const float mu5 = r5 - 5.0f * m1 * r4 + 10.0f * m2 * r3 - 10.0f * m3 * r2
                      + 4.0f * m3 * m2;

    const int j = col * NM;
    g_cum[j + 0] = m1 - mu[j + 0];
    g_cum[j + 1] = 0.f - mu[j + 1];
    g_cum[j + 2] = mu2 - mu[j + 2];
    g_cum[j + 3] = (mu3 - 3.0f * mu2 * mu2) - mu[j + 3];
    g_cum[j + 4] = (mu5 - 10.0f * mu2 * mu3) - mu[j + 4];
}

__global__ void k_project_gen(const float* __restrict__ W, float* __restrict__ out,
                              int P5, int K) {
    const int w = blockIdx.x;
    const int lane = threadIdx.x;
    float acc = 0.f;
    for (int i = lane; i < P5; i += 32)
        acc += g_cum[i] * W[(size_t)i * K + w];
#pragma unroll
    for (int o = 16; o > 0; o >>= 1)
        acc += __shfl_down_sync(0xffffffffu, acc, o);
    if (lane == 0) out[w] = acc;
}

// ---------------------------------------------------------------------------
extern "C" void kernel_launch(void* const* d_in, const int* in_sizes, int n_in,
                              void* d_out, int out_size) {
    const float* X  = (const float*)d_in[0];
    const float* mu = (const float*)d_in[1];
    const float* W  = (const float*)d_in[2];
    float* out = (float*)d_out;

    const int P5 = in_sizes[1];          // P * 5
    const int P  = P5 / NM;              // 1024
    const int N  = in_sizes[0] / P;      // 100000
    const int K  = in_sizes[2] / P5;     // 8

    if (K == 8 && P == 1024) {
        k_fused<<<GTOT, 256>>>(X, mu, W, out, N);
    } else {
        const int Gg = GTOT;
        k_moments<<<Gg, P / 4>>>(X, N, P, Gg);
        k_reduceB_gen<<<(P + 127) / 128, 128>>>(mu, N, P, Gg);
        k_project_gen<<<K, 32>>>(W, out, P5, K);
    }
}